// round 14
// baseline (speedup 1.0000x reference)
#include <cuda_runtime.h>
#include <cuda_bf16.h>
#include <stdint.h>

#define NPW 16
#define M   64
#define NT  1024           // 32 warps, 8/SMSP
#define NW  (NT / 32)
#define NG  16             // row groups for m^2 phases: 16 groups x 4 rows
#define OBJ 10
#define DSTR 68            // dsT row stride (floats)

#define MAGIC 12582912.0f  // 1.5*2^23; bits(MAGIC + m) = 0x4B400000 + m

// Dynamic shared memory layout (bytes); all offsets 16B-aligned
#define OFF_DST   0u          // dsT[j*68 + l], pre-scaled by 16, in [0,16)  (17408)
#define OFF_SIM   17408u      // (16384)
#define OFF_AM    33792u      // (16384)
#define OFF_T03   50176u      // float4[19*16]  f0 .xy / f3 .zw       (4864)
#define OFF_T14   55040u      // float4[19*16]  f1 .xy / f4 .zw       (4864)
#define OFF_HOT   59904u      // signed-u f2 table: 32 slots x 16 reps x 8B (4096)
#define TBASE     61952u      // slot m=0 center; m in [-16,15] at TBASE + m*128
#define OFF_T6    64000u      // float2[19*16]                        (2432)
#define OFF_T5    66432u      // float2[19*16]                        (2432)
#define OFF_T7    68864u      // float2[19] + pad                     (160)
#define OFF_TAB   69024u      // float2[8*17] (csum, w_next)          (1088)
#define OFF_ATT   70112u
#define OFF_AREA  70368u
#define OFF_BX1   70624u
#define OFF_BY1   70880u
#define OFF_BX2   71136u
#define OFF_BY2   71392u
#define OFF_PART  71648u      // NG*64*4 = 4096
#define OFF_RINV  75744u
#define OFF_WRA   76000u      // 32 floats
#define OFF_WRB   76128u      // 32 floats
#define SMEM_TOTAL 76256u

// Protected magic-add: __fadd_rn is never merged/reassociated, so fast-math
// cannot refold bias constants into MAGIC (the R5/R6 bug).
__device__ __forceinline__ uint32_t magic_bits(float t) {
    return __float_as_uint(__fadd_rn(t, MAGIC));
}

// Fused-table entry for slot = n+1 (n = -1..17):
//   val(x) = T0 + (16x)*T1 on segment n, T0 = csum[n] - n*w_next, T1 = w_next.
//   slot 0 (n=-1) encodes the reference's x<0 branch.
__device__ __forceinline__ float2 fused_entry(const float2* __restrict__ t, int slot) {
    if (slot == 0) {
        float cs0 = t[0].x, w1 = t[0].y;
        return make_float2(cs0 + w1, w1);
    }
    int n = slot - 1; if (n > 16) n = 16;
    float2 v = t[n];
    return make_float2(fmaf(-(float)n, v.y, v.x), v.y);
}

__global__ __launch_bounds__(NT, 1)
void counter_kernel(const float* __restrict__ boxes,   // (n,4,64)
                    const float* __restrict__ attn,    // (n,64)
                    const float* __restrict__ fw,      // (16,17)
                    float* __restrict__ out)           // (n,11)
{
    extern __shared__ char smem[];
    const int tid  = threadIdx.x;
    const int bi   = blockIdx.x;
    const int lane = tid & 31;
    const int wid  = tid >> 5;
    const unsigned FULL = 0xffffffffu;

    float*  dsT    = (float*)(smem + OFF_DST);
    float*  sim    = (float*)(smem + OFF_SIM);
    float*  Am     = (float*)(smem + OFF_AM);
    float2* tab    = (float2*)(smem + OFF_TAB);
    float*  att_s  = (float*)(smem + OFF_ATT);
    float*  area_s = (float*)(smem + OFF_AREA);
    float*  sbx1   = (float*)(smem + OFF_BX1);
    float*  sby1   = (float*)(smem + OFF_BY1);
    float*  sbx2   = (float*)(smem + OFF_BX2);
    float*  sby2   = (float*)(smem + OFF_BY2);
    float*  part   = (float*)(smem + OFF_PART);
    float*  rowinv = (float*)(smem + OFF_RINV);
    float*  wredA  = (float*)(smem + OFF_WRA);
    float*  wredB  = (float*)(smem + OFF_WRB);

    // Fused address constants (uint32 wrap): addr = zbits*stride + C.
    // zbits*128 wraps to 0xA0000000 + m*128; zbits*256 to 0x40000000 + m*256.
    const uint32_t lrep = (uint32_t)(tid & 15);
    const uint32_t CHOT = (TBASE   + lrep * 8u)          - 0xA0000000u;  // signed-u hot
    const uint32_t C2_6 = (OFF_T6  + lrep * 8u  + 128u)  - 0xA0000000u;
    const uint32_t C2_5 = (OFF_T5  + lrep * 8u  + 128u)  - 0xA0000000u;
    const uint32_t C403 = (OFF_T03 + lrep * 16u + 256u)  - 0x40000000u;
    const uint32_t C414 = (OFF_T14 + lrep * 16u + 256u)  - 0x40000000u;

    // ---- Phase 0: serial proven table build (threads 0..7) + input loads ----
    if (tid < 8) {
        const int fn = tid;
        float w[NPW + 1];
        float s = 0.0f;
        #pragma unroll
        for (int i = 0; i <= NPW; i++) { w[i] = fabsf(fw[fn * 17 + i]); s += w[i]; }
        #pragma unroll
        for (int i = 0; i <= NPW; i++) w[i] = w[i] / s;
        float c = 0.0f;
        #pragma unroll
        for (int i = 0; i <= NPW; i++) {
            c += w[i];
            float wn = w[(i + 1 <= NPW) ? (i + 1) : NPW];
            tab[fn * 17 + i] = make_float2(c, wn);
        }
    }
    if (wid >= 8 && wid < 10) {
        const int j = tid - 256;
        att_s[j] = attn[bi * M + j];
        float x1 = boxes[(bi * 4 + 0) * M + j];
        float y1 = boxes[(bi * 4 + 1) * M + j];
        float x2 = boxes[(bi * 4 + 2) * M + j];
        float y2 = boxes[(bi * 4 + 3) * M + j];
        sbx1[j] = x1; sby1[j] = y1; sbx2[j] = x2; sby2[j] = y2;
        area_s[j] = fmaxf(x2 - x1, 0.0f) * fmaxf(y2 - y1, 0.0f);
    }
    __syncthreads();

    // ---- Phase 1a: derive packed, 16x lane-replicated cold tables ----
    if (tid < 19 * 16) {
        const uint32_t slot = (uint32_t)(tid >> 4);
        const uint32_t rep  = (uint32_t)(tid & 15);
        float2 e0 = fused_entry(tab + 0 * 17, slot);
        float2 e3 = fused_entry(tab + 3 * 17, slot);
        *(float4*)(smem + OFF_T03 + slot * 256u + rep * 16u) =
            make_float4(e0.x, 16.0f * e0.y, e3.x, 16.0f * e3.y);
        float2 e1 = fused_entry(tab + 1 * 17, slot);
        float2 e4 = fused_entry(tab + 4 * 17, slot);
        *(float4*)(smem + OFF_T14 + slot * 256u + rep * 16u) =
            make_float4(e1.x, 16.0f * e1.y, e4.x, 16.0f * e4.y);
        float2 e5 = fused_entry(tab + 5 * 17, slot);
        *(float2*)(smem + OFF_T5 + slot * 128u + rep * 8u) =
            make_float2(e5.x, 16.0f * e5.y);
        float2 e6 = fused_entry(tab + 6 * 17, slot);
        *(float2*)(smem + OFF_T6 + slot * 128u + rep * 8u) =
            make_float2(e6.x, 16.0f * e6.y);
        if (rep == 0) {
            float2 e7 = fused_entry(tab + 7 * 17, slot);
            *(float2*)(smem + OFF_T7 + slot * 8u) = make_float2(e7.x, 16.0f * e7.y);
        }
    }

    // ---- Phase 1b: SIGNED-u hot f2 table into shared (16x lane-replicated) ----
    // e(u) = f2(scaled 1-|u|/16) over u in (-16,16): 32 knot classes
    // m = rni(u') with u' = u - 0.5. Slot m at TBASE + m*128 (m<0 below base).
    //   m >= 0: segment n = 15-m: e = (U0 - 0.5*sl) + u'*(-sl)
    //   m <  0: segment n = m+16: e = (U0 + 0.5*sl) + u'*(+sl)
    if (tid < 512) {
        const int s   = tid >> 4;                    // 0..31
        const int rep = tid & 15;
        const int m   = (s < 16) ? s : (s - 32);     // [-16,15]
        const int n   = (m >= 0) ? (15 - m) : (m + 16);
        float2 e2 = fused_entry(tab + 2 * 17, n + 1);
        float sl = e2.y;
        float U0 = fmaf(16.0f, sl, e2.x);
        float A  = (m >= 0) ? fmaf(-0.5f, sl, U0) : fmaf(0.5f, sl, U0);
        float B  = (m >= 0) ? -sl : sl;
        *(float2*)(smem + TBASE + m * 128 + rep * 8) = make_float2(A, B);
    }
    __syncthreads();

    // ---- Phase 2: ds16 (transposed, clamped to [0,16)), Am, dconf, attconf ----
    const int c = tid & 63;
    const int g = tid >> 6;                        // 0..15: 4 rows each
    const float attc = att_s[c];

    float attconf = 0.0f;
    if (tid < M) {
        float x = att_s[tid];
        uint32_t zb = magic_bits(__fmaf_rn(x, 16.0f, -0.5f));
        float2 v = *(const float2*)(smem + (zb * 128u + C2_5));
        attconf = fabsf(fmaf(x, v.y, v.x) - 0.5f);
    }

    float dconf = 0.0f;
    {
        const float x1c = sbx1[c], y1c = sby1[c], x2c = sbx2[c], y2c = sby2[c];
        const float arc = area_s[c];
        #pragma unroll
        for (int it = 0; it < 4; it++) {
            const int r = g + NG * it;
            float rel = att_s[r] * attc;
            uint32_t zb0 = magic_bits(__fmaf_rn(rel, 16.0f, -0.5f));
            float4 v03 = *(const float4*)(smem + (zb0 * 256u + C403));
            float f0v = fmaf(rel, v03.y, v03.x);
            float f3v = fmaf(rel, v03.w, v03.z);

            float ix = fminf(sbx2[r], x2c) - fmaxf(sbx1[r], x1c);
            float iy = fminf(sby2[r], y2c) - fmaxf(sby1[r], y1c);
            ix = fmaxf(ix, 0.0f); iy = fmaxf(iy, 0.0f);
            float inter = ix * iy;
            float den   = area_s[r] + arc - inter + 1e-12f;
            float dist  = 1.0f - inter / den;

            uint32_t zb1 = magic_bits(__fmaf_rn(dist, 16.0f, -0.5f));
            float4 v14 = *(const float4*)(smem + (zb1 * 256u + C414));
            float f1v = fmaf(dist, v14.y, v14.x);
            float f4v = fmaf(dist, v14.w, v14.z);
            float2 v6 = *(const float2*)(smem + (zb1 * 128u + C2_6));
            float f6v = fmaf(dist, v6.y, v6.x);

            float dsv = 16.0f * (f3v * f4v);
            dsv = fminf(fmaxf(dsv, 0.0f), 15.999999f);   // |u| < 16 strictly

            Am[r * M + c]     = f0v * f1v;
            dsT[c * DSTR + r] = dsv;
            dconf += fabsf(f6v - 0.5f);
        }
    }

    // sim diagonal: f2(1)^65; csum2[16] from the base table
    if (tid < M) {
        float cv = tab[2 * 17 + NPW].x;
        float c2 = cv * cv, c4 = c2 * c2, c8 = c4 * c4;
        float c16 = c8 * c8, c32 = c16 * c16, c64 = c32 * c32;
        sim[tid * M + tid] = c64 * cv;
    }
    __syncthreads();

    // ---- Phase 3: hot m^3 loop; j-sharing slots, software-pipelined ----
    // Slot = (j, k1=j+1+2o, k2=k1+1): two pairs share row j -> 3 row loads.
    // Enumerated by (o, j): cum(o) = o*(64-o); exactly 1024 slots.
    int sj, sk1, sk2;
    {
        int p = tid;
        float s = __fsqrt_rn((float)(1024 - p));   // exact at boundaries
        int si = (int)s;
        int o = 32 - (si + (((float)si < s) ? 1 : 0));   // 32 - ceil(s)
        o = (o < 0) ? 0 : ((o > 31) ? 31 : o);
        if (p <  o * (64 - o) && o > 0)  o--;
        if (p >= (o + 1) * (63 - o) && o < 31) o++;
        if (p <  o * (64 - o) && o > 0)  o--;
        int j = p - o * (64 - o);
        int jmax = 62 - 2 * o;
        j = (j < 0) ? 0 : ((j > jmax) ? jmax : j);
        sj  = j;
        sk1 = j + 1 + 2 * o;                // <= 63
        sk2 = (sk1 < 63) ? (sk1 + 1) : 63;  // last slot of odd row: duplicate
    }
    const float* pj  = dsT + sj  * DSTR;
    const float* pk1 = dsT + sk1 * DSTR;
    const float* pk2 = dsT + sk2 * DSTR;

    float prod1 = 1.0f, prod2 = 1.0f;

    float4 a0 = *(const float4*)(pj);
    float4 b0 = *(const float4*)(pk1);
    float4 c0 = *(const float4*)(pk2);

    #pragma unroll 4
    for (int lb = 0; lb < M; lb += 4) {
        // prefetch next block (row padding makes the lb=60 over-read safe)
        float4 a1 = *(const float4*)(pj  + lb + 4);
        float4 b1 = *(const float4*)(pk1 + lb + 4);
        float4 c1 = *(const float4*)(pk2 + lb + 4);

        // am = a - 0.5 (shared by both pairs)
        float am0 = a0.x - 0.5f, am1 = a0.y - 0.5f;
        float am2 = a0.z - 0.5f, am3 = a0.w - 0.5f;

        float u0 = am0 - b0.x, u1 = am1 - b0.y, u2 = am2 - b0.z, u3 = am3 - b0.w;
        float v0 = am0 - c0.x, v1 = am1 - c0.y, v2 = am2 - c0.z, v3 = am3 - c0.w;

        uint32_t zu0 = magic_bits(u0);
        uint32_t zu1 = magic_bits(u1);
        uint32_t zu2 = magic_bits(u2);
        uint32_t zu3 = magic_bits(u3);
        uint32_t zv0 = magic_bits(v0);
        uint32_t zv1 = magic_bits(v1);
        uint32_t zv2 = magic_bits(v2);
        uint32_t zv3 = magic_bits(v3);

        float2 tu0 = *(const float2*)(smem + (zu0 * 128u + CHOT));
        float2 tu1 = *(const float2*)(smem + (zu1 * 128u + CHOT));
        float2 tu2 = *(const float2*)(smem + (zu2 * 128u + CHOT));
        float2 tu3 = *(const float2*)(smem + (zu3 * 128u + CHOT));
        float2 tv0 = *(const float2*)(smem + (zv0 * 128u + CHOT));
        float2 tv1 = *(const float2*)(smem + (zv1 * 128u + CHOT));
        float2 tv2 = *(const float2*)(smem + (zv2 * 128u + CHOT));
        float2 tv3 = *(const float2*)(smem + (zv3 * 128u + CHOT));

        float e0 = fmaf(u0, tu0.y, tu0.x);
        float e1 = fmaf(u1, tu1.y, tu1.x);
        float e2 = fmaf(u2, tu2.y, tu2.x);
        float e3 = fmaf(u3, tu3.y, tu3.x);
        float f0 = fmaf(v0, tv0.y, tv0.x);
        float f1 = fmaf(v1, tv1.y, tv1.x);
        float f2 = fmaf(v2, tv2.y, tv2.x);
        float f3 = fmaf(v3, tv3.y, tv3.x);

        prod1 *= (e0 * e1) * (e2 * e3);
        prod2 *= (f0 * f1) * (f2 * f3);

        a0 = a1; b0 = b1; c0 = c1;
    }

    // att factor + sim writes
    {
        float attj = att_s[sj];
        float d1 = attj - att_s[sk1];
        float d2 = attj - att_s[sk2];
        float u1 = __fmaf_rn(16.0f, d1, -0.5f);   // u' = 16*diff - 0.5
        float u2 = __fmaf_rn(16.0f, d2, -0.5f);
        uint32_t z1 = magic_bits(u1);
        uint32_t z2 = magic_bits(u2);
        float2 t1 = *(const float2*)(smem + (z1 * 128u + CHOT));
        float2 t2 = *(const float2*)(smem + (z2 * 128u + CHOT));
        float sv1 = prod1 * fmaf(u1, t1.y, t1.x);
        float sv2 = prod2 * fmaf(u2, t2.y, t2.x);
        sim[sj  * M + sk1] = sv1;
        sim[sk1 * M + sj ] = sv1;
        sim[sj  * M + sk2] = sv2;
        sim[sk2 * M + sj ] = sv2;
    }
    __syncthreads();

    // ---- Phase 4: row sums (column-wise, conflict-free) -> rowinv ----
    {
        float s = 0.0f;
        #pragma unroll
        for (int it = 0; it < 4; it++)
            s += sim[(g + NG * it) * M + c];
        part[g * M + c] = s;
    }
    __syncthreads();
    if (tid < M) {
        float rs = 0.0f;
        #pragma unroll
        for (int gg = 0; gg < NG; gg++) rs += part[gg * M + tid];
        rowinv[tid] = 1.0f / rs;
    }
    __syncthreads();

    // ---- Phase 5: score accumulation (Am reused) ----
    float accA = 0.0f;
    #pragma unroll
    for (int it = 0; it < 4; it++) {
        const int r = g + NG * it;
        accA += Am[r * M + c] * rowinv[r];
    }
    accA *= rowinv[c];

    float corr = 0.0f;
    if (tid < M) {
        float a = att_s[tid];
        float aa = a * a;
        uint32_t zb = magic_bits(__fmaf_rn(aa, 16.0f, -0.5f));
        float4 v03 = *(const float4*)(smem + (zb * 256u + C403));
        corr = fmaf(aa, v03.y, v03.x) * rowinv[tid];
    }

    float ra  = accA + corr;
    float rbv = dconf * (1.0f / 4096.0f) + attconf * (1.0f / 64.0f);
    #pragma unroll
    for (int off = 16; off > 0; off >>= 1) {
        ra  += __shfl_down_sync(FULL, ra,  off);
        rbv += __shfl_down_sync(FULL, rbv, off);
    }
    if (lane == 0) { wredA[wid] = ra; wredB[wid] = rbv; }
    __syncthreads();

    // ---- Phase 6: score -> one-hot * conf ----
    if (tid == 0) {
        float S = 0.0f, B = 0.0f;
        #pragma unroll
        for (int i = 0; i < NW; i++) { S += wredA[i]; B += wredB[i]; }

        float score = sqrtf(S + 1e-20f);
        uint32_t zb = magic_bits(__fmaf_rn(B, 16.0f, -0.5f));
        int slot = (int)(zb - 0x4B3FFFFFu);
        slot = (slot < 0) ? 0 : ((slot > 18) ? 18 : slot);
        float2 v7 = *(const float2*)(smem + OFF_T7 + (uint32_t)slot * 8u);
        float conf = fmaf(B, v7.y, v7.x);

        float sc = fminf(fmaxf(score, 0.0f), (float)OBJ);
        int   i0 = (int)sc;
        float fr = sc - floorf(sc);
        int   i1 = (i0 + 1 <= OBJ) ? (i0 + 1) : OBJ;

        #pragma unroll
        for (int o = 0; o <= OBJ; o++) {
            float v = 0.0f;
            if (o == i0) v += (1.0f - fr);
            if (o == i1) v += fr;
            out[bi * (OBJ + 1) + o] = conf * v;
        }
    }
}

extern "C" void kernel_launch(void* const* d_in, const int* in_sizes, int n_in,
                              void* d_out, int out_size) {
    const float* boxes = (const float*)d_in[0];   // (n,4,64)
    const float* attn  = (const float*)d_in[1];   // (n,64)
    const float* fwts  = (const float*)d_in[2];   // (16,17)
    float* out = (float*)d_out;                   // (n,11)

    cudaFuncSetAttribute(counter_kernel,
                         cudaFuncAttributeMaxDynamicSharedMemorySize, SMEM_TOTAL);

    const int n = in_sizes[1] / M;                // 128
    counter_kernel<<<n, NT, SMEM_TOTAL>>>(boxes, attn, fwts, out);
}

// round 15
// speedup vs baseline: 1.1194x; 1.1194x over previous
#include <cuda_runtime.h>
#include <cuda_bf16.h>
#include <stdint.h>

#define NPW 16
#define M   64
#define NT  1024           // 32 warps, 8/SMSP
#define NW  (NT / 32)
#define NG  16             // row groups for m^2 phases: 16 groups x 4 rows
#define OBJ 10
#define DSTR 68            // dsT row stride (floats)

#define MAGIC 12582912.0f  // 1.5*2^23; bits(MAGIC + m) = 0x4B400000 + m

// Dynamic shared memory layout (bytes); all offsets 16B-aligned
#define OFF_DST   0u          // dsT[j*68 + l], pre-scaled by 16, in [0,16)  (17408)
#define OFF_SIM   17408u      // (16384)
#define OFF_AM    33792u      // (16384)
#define OFF_T03   50176u      // float4[19*16]  f0 .xy / f3 .zw       (4864)
#define OFF_T14   55040u      // float4[19*16]  f1 .xy / f4 .zw       (4864)
#define OFF_T6    62336u      // float2[19*16]                        (2432)
#define OFF_T5    64768u      // float2[19*16]                        (2432)
#define OFF_T7    67200u      // float2[19] + pad                     (160)
#define OFF_TAB   67360u      // float2[8*17] (csum, w_next)          (1088)
#define OFF_ATT   68448u
#define OFF_AREA  68704u
#define OFF_BX1   68960u
#define OFF_BY1   69216u
#define OFF_BX2   69472u
#define OFF_BY2   69728u
#define OFF_PART  69984u      // NG*64*4 = 4096
#define OFF_RINV  74080u
#define OFF_WRA   74336u      // 32 floats
#define OFF_WRB   74464u      // 32 floats
#define SMEM_TOTAL 74592u

// Protected magic-add: __fadd_rn is never merged/reassociated, so fast-math
// cannot refold bias constants into MAGIC (the R5/R6 bug).
__device__ __forceinline__ uint32_t magic_bits(float t) {
    return __float_as_uint(__fadd_rn(t, MAGIC));
}

// Fused-table entry for slot = n+1 (n = -1..17):
//   val(x) = T0 + (16x)*T1 on segment n, T0 = csum[n] - n*w_next, T1 = w_next.
//   slot 0 (n=-1) encodes the reference's x<0 branch.
__device__ __forceinline__ float2 fused_entry(const float2* __restrict__ t, int slot) {
    if (slot == 0) {
        float cs0 = t[0].x, w1 = t[0].y;
        return make_float2(cs0 + w1, w1);
    }
    int n = slot - 1; if (n > 16) n = 16;
    float2 v = t[n];
    return make_float2(fmaf(-(float)n, v.y, v.x), v.y);
}

__global__ __launch_bounds__(NT, 1)
void counter_kernel(const float* __restrict__ boxes,   // (n,4,64)
                    const float* __restrict__ attn,    // (n,64)
                    const float* __restrict__ fw,      // (16,17)
                    float* __restrict__ out)           // (n,11)
{
    extern __shared__ char smem[];
    const int tid  = threadIdx.x;
    const int bi   = blockIdx.x;
    const int lane = tid & 31;
    const int wid  = tid >> 5;
    const unsigned FULL = 0xffffffffu;

    float*  dsT    = (float*)(smem + OFF_DST);
    float*  sim    = (float*)(smem + OFF_SIM);
    float*  Am     = (float*)(smem + OFF_AM);
    float2* tab    = (float2*)(smem + OFF_TAB);
    float*  att_s  = (float*)(smem + OFF_ATT);
    float*  area_s = (float*)(smem + OFF_AREA);
    float*  sbx1   = (float*)(smem + OFF_BX1);
    float*  sby1   = (float*)(smem + OFF_BY1);
    float*  sbx2   = (float*)(smem + OFF_BX2);
    float*  sby2   = (float*)(smem + OFF_BY2);
    float*  part   = (float*)(smem + OFF_PART);
    float*  rowinv = (float*)(smem + OFF_RINV);
    float*  wredA  = (float*)(smem + OFF_WRA);
    float*  wredB  = (float*)(smem + OFF_WRB);

    // Fused address constants for the (cold) packed tables (uint32 wrap).
    const uint32_t lrep = (uint32_t)(tid & 15);
    const uint32_t C2_6 = (OFF_T6  + lrep * 8u  + 128u)  - 0xA0000000u;
    const uint32_t C2_5 = (OFF_T5  + lrep * 8u  + 128u)  - 0xA0000000u;
    const uint32_t C403 = (OFF_T03 + lrep * 16u + 256u)  - 0x40000000u;
    const uint32_t C414 = (OFF_T14 + lrep * 16u + 256u)  - 0x40000000u;

    // ---- Phase 0: serial proven table build (threads 0..7) + input loads ----
    if (tid < 8) {
        const int fn = tid;
        float w[NPW + 1];
        float s = 0.0f;
        #pragma unroll
        for (int i = 0; i <= NPW; i++) { w[i] = fabsf(fw[fn * 17 + i]); s += w[i]; }
        #pragma unroll
        for (int i = 0; i <= NPW; i++) w[i] = w[i] / s;
        float c = 0.0f;
        #pragma unroll
        for (int i = 0; i <= NPW; i++) {
            c += w[i];
            float wn = w[(i + 1 <= NPW) ? (i + 1) : NPW];
            tab[fn * 17 + i] = make_float2(c, wn);
        }
    }
    if (wid >= 8 && wid < 10) {
        const int j = tid - 256;
        att_s[j] = attn[bi * M + j];
        float x1 = boxes[(bi * 4 + 0) * M + j];
        float y1 = boxes[(bi * 4 + 1) * M + j];
        float x2 = boxes[(bi * 4 + 2) * M + j];
        float y2 = boxes[(bi * 4 + 3) * M + j];
        sbx1[j] = x1; sby1[j] = y1; sbx2[j] = x2; sby2[j] = y2;
        area_s[j] = fmaxf(x2 - x1, 0.0f) * fmaxf(y2 - y1, 0.0f);
    }
    __syncthreads();

    // ---- Phase 1a: derive packed, 16x lane-replicated cold tables ----
    if (tid < 19 * 16) {
        const uint32_t slot = (uint32_t)(tid >> 4);
        const uint32_t rep  = (uint32_t)(tid & 15);
        float2 e0 = fused_entry(tab + 0 * 17, slot);
        float2 e3 = fused_entry(tab + 3 * 17, slot);
        *(float4*)(smem + OFF_T03 + slot * 256u + rep * 16u) =
            make_float4(e0.x, 16.0f * e0.y, e3.x, 16.0f * e3.y);
        float2 e1 = fused_entry(tab + 1 * 17, slot);
        float2 e4 = fused_entry(tab + 4 * 17, slot);
        *(float4*)(smem + OFF_T14 + slot * 256u + rep * 16u) =
            make_float4(e1.x, 16.0f * e1.y, e4.x, 16.0f * e4.y);
        float2 e5 = fused_entry(tab + 5 * 17, slot);
        *(float2*)(smem + OFF_T5 + slot * 128u + rep * 8u) =
            make_float2(e5.x, 16.0f * e5.y);
        float2 e6 = fused_entry(tab + 6 * 17, slot);
        *(float2*)(smem + OFF_T6 + slot * 128u + rep * 8u) =
            make_float2(e6.x, 16.0f * e6.y);
        if (rep == 0) {
            float2 e7 = fused_entry(tab + 7 * 17, slot);
            *(float2*)(smem + OFF_T7 + slot * 8u) = make_float2(e7.x, 16.0f * e7.y);
        }
    }

    // ---- Phase 1b: SIGNED-u hot f2 table into warp registers ----
    // e(u) = f2(scaled 1-|u|/16) is continuous piecewise-linear in
    // u = ds_j - ds_k over (-16,16): 32 integer-knot classes m = floor(u).
    // lane = m mod 32; shuffle index = raw magic bits of u' = u - 0.5.
    float shA, shB;
    {
        int n = (lane < 16) ? (15 - lane) : (lane - 16);
        float2 e2 = fused_entry(tab + 2 * 17, n + 1);
        float U0 = fmaf(16.0f, e2.y, e2.x);       // value at d=0 on segment n
        if (lane < 16) { shA = fmaf(-0.5f, e2.y, U0); shB = -e2.y; }
        else           { shA = fmaf( 0.5f, e2.y, U0); shB =  e2.y; }
    }
    __syncthreads();

    // ---- Phase 2: ds16 (transposed, clamped to [0,16)), Am, dconf, attconf ----
    const int c = tid & 63;
    const int g = tid >> 6;                        // 0..15: 4 rows each
    const float attc = att_s[c];

    float attconf = 0.0f;
    if (tid < M) {
        float x = att_s[tid];
        uint32_t zb = magic_bits(__fmaf_rn(x, 16.0f, -0.5f));
        float2 v = *(const float2*)(smem + (zb * 128u + C2_5));
        attconf = fabsf(fmaf(x, v.y, v.x) - 0.5f);
    }

    float dconf = 0.0f;
    {
        const float x1c = sbx1[c], y1c = sby1[c], x2c = sbx2[c], y2c = sby2[c];
        const float arc = area_s[c];
        #pragma unroll
        for (int it = 0; it < 4; it++) {
            const int r = g + NG * it;
            float rel = att_s[r] * attc;
            uint32_t zb0 = magic_bits(__fmaf_rn(rel, 16.0f, -0.5f));
            float4 v03 = *(const float4*)(smem + (zb0 * 256u + C403));
            float f0v = fmaf(rel, v03.y, v03.x);
            float f3v = fmaf(rel, v03.w, v03.z);

            float ix = fminf(sbx2[r], x2c) - fmaxf(sbx1[r], x1c);
            float iy = fminf(sby2[r], y2c) - fmaxf(sby1[r], y1c);
            ix = fmaxf(ix, 0.0f); iy = fmaxf(iy, 0.0f);
            float inter = ix * iy;
            float den   = area_s[r] + arc - inter + 1e-12f;
            float dist  = 1.0f - inter / den;

            uint32_t zb1 = magic_bits(__fmaf_rn(dist, 16.0f, -0.5f));
            float4 v14 = *(const float4*)(smem + (zb1 * 256u + C414));
            float f1v = fmaf(dist, v14.y, v14.x);
            float f4v = fmaf(dist, v14.w, v14.z);
            float2 v6 = *(const float2*)(smem + (zb1 * 128u + C2_6));
            float f6v = fmaf(dist, v6.y, v6.x);

            float dsv = 16.0f * (f3v * f4v);
            dsv = fminf(fmaxf(dsv, 0.0f), 15.999999f);   // |u| < 16 strictly

            Am[r * M + c]     = f0v * f1v;
            dsT[c * DSTR + r] = dsv;
            dconf += fabsf(f6v - 0.5f);
        }
    }

    // sim diagonal: f2(1)^65; csum2[16] from the base table
    if (tid < M) {
        float cv = tab[2 * 17 + NPW].x;
        float c2 = cv * cv, c4 = c2 * c2, c8 = c4 * c4;
        float c16 = c8 * c8, c32 = c16 * c16, c64 = c32 * c32;
        sim[tid * M + tid] = c64 * cv;
    }
    __syncthreads();

    // ---- Phase 3: hot m^3 loop; j-sharing slots, software-pipelined ----
    // Slot = (j, k1=j+1+2o, k2=k1+1): two pairs share row j -> 3 row loads.
    // Enumerated by (o, j): cum(o) = o*(64-o); exactly 1024 slots.
    int sj, sk1, sk2;
    {
        int p = tid;
        float s = __fsqrt_rn((float)(1024 - p));   // exact at boundaries
        int si = (int)s;
        int o = 32 - (si + (((float)si < s) ? 1 : 0));   // 32 - ceil(s)
        o = (o < 0) ? 0 : ((o > 31) ? 31 : o);
        if (p <  o * (64 - o) && o > 0)  o--;
        if (p >= (o + 1) * (63 - o) && o < 31) o++;
        if (p <  o * (64 - o) && o > 0)  o--;
        int j = p - o * (64 - o);
        int jmax = 62 - 2 * o;
        j = (j < 0) ? 0 : ((j > jmax) ? jmax : j);
        sj  = j;
        sk1 = j + 1 + 2 * o;                // <= 63
        sk2 = (sk1 < 63) ? (sk1 + 1) : 63;  // last slot of odd row: duplicate
    }
    const float* pj  = dsT + sj  * DSTR;
    const float* pk1 = dsT + sk1 * DSTR;
    const float* pk2 = dsT + sk2 * DSTR;

    float prod1 = 1.0f, prod2 = 1.0f;

    float4 a0 = *(const float4*)(pj);
    float4 b0 = *(const float4*)(pk1);
    float4 c0 = *(const float4*)(pk2);

    #pragma unroll 4
    for (int lb = 0; lb < M; lb += 4) {
        // Unconditional prefetch: the lb=60 over-read hits floats
        // 4348..4351 of the 4352-float dsT region -- in-bounds.
        float4 a1 = *(const float4*)(pj  + lb + 4);
        float4 b1 = *(const float4*)(pk1 + lb + 4);
        float4 c1 = *(const float4*)(pk2 + lb + 4);

        // am = a - 0.5 (shared by both pairs)
        float am0 = a0.x - 0.5f, am1 = a0.y - 0.5f;
        float am2 = a0.z - 0.5f, am3 = a0.w - 0.5f;

        float u0 = am0 - b0.x, u1 = am1 - b0.y, u2 = am2 - b0.z, u3 = am3 - b0.w;
        float v0 = am0 - c0.x, v1 = am1 - c0.y, v2 = am2 - c0.z, v3 = am3 - c0.w;

        int zu0 = (int)magic_bits(u0);
        int zu1 = (int)magic_bits(u1);
        int zu2 = (int)magic_bits(u2);
        int zu3 = (int)magic_bits(u3);
        int zv0 = (int)magic_bits(v0);
        int zv1 = (int)magic_bits(v1);
        int zv2 = (int)magic_bits(v2);
        int zv3 = (int)magic_bits(v3);

        float Au0 = __shfl_sync(FULL, shA, zu0);
        float Bu0 = __shfl_sync(FULL, shB, zu0);
        float Au1 = __shfl_sync(FULL, shA, zu1);
        float Bu1 = __shfl_sync(FULL, shB, zu1);
        float Au2 = __shfl_sync(FULL, shA, zu2);
        float Bu2 = __shfl_sync(FULL, shB, zu2);
        float Au3 = __shfl_sync(FULL, shA, zu3);
        float Bu3 = __shfl_sync(FULL, shB, zu3);
        float Av0 = __shfl_sync(FULL, shA, zv0);
        float Bv0 = __shfl_sync(FULL, shB, zv0);
        float Av1 = __shfl_sync(FULL, shA, zv1);
        float Bv1 = __shfl_sync(FULL, shB, zv1);
        float Av2 = __shfl_sync(FULL, shA, zv2);
        float Bv2 = __shfl_sync(FULL, shB, zv2);
        float Av3 = __shfl_sync(FULL, shA, zv3);
        float Bv3 = __shfl_sync(FULL, shB, zv3);

        float e0 = fmaf(u0, Bu0, Au0);
        float e1 = fmaf(u1, Bu1, Au1);
        float e2 = fmaf(u2, Bu2, Au2);
        float e3 = fmaf(u3, Bu3, Au3);
        float f0 = fmaf(v0, Bv0, Av0);
        float f1 = fmaf(v1, Bv1, Av1);
        float f2 = fmaf(v2, Bv2, Av2);
        float f3 = fmaf(v3, Bv3, Av3);

        prod1 *= (e0 * e1) * (e2 * e3);
        prod2 *= (f0 * f1) * (f2 * f3);

        a0 = a1; b0 = b1; c0 = c1;
    }

    // att factor + sim writes
    {
        float attj = att_s[sj];
        float d1 = attj - att_s[sk1];
        float d2 = attj - att_s[sk2];
        float u1 = __fmaf_rn(16.0f, d1, -0.5f);   // u' = 16*diff - 0.5
        float u2 = __fmaf_rn(16.0f, d2, -0.5f);
        int z1 = (int)magic_bits(u1);
        int z2 = (int)magic_bits(u2);
        float A1 = __shfl_sync(FULL, shA, z1);
        float B1 = __shfl_sync(FULL, shB, z1);
        float A2 = __shfl_sync(FULL, shA, z2);
        float B2 = __shfl_sync(FULL, shB, z2);
        float sv1 = prod1 * fmaf(u1, B1, A1);
        float sv2 = prod2 * fmaf(u2, B2, A2);
        sim[sj  * M + sk1] = sv1;
        sim[sk1 * M + sj ] = sv1;
        sim[sj  * M + sk2] = sv2;
        sim[sk2 * M + sj ] = sv2;
    }
    __syncthreads();

    // ---- Phase 4: row sums (column-wise, conflict-free) -> rowinv ----
    {
        float s = 0.0f;
        #pragma unroll
        for (int it = 0; it < 4; it++)
            s += sim[(g + NG * it) * M + c];
        part[g * M + c] = s;
    }
    __syncthreads();
    if (tid < M) {
        float rs = 0.0f;
        #pragma unroll
        for (int gg = 0; gg < NG; gg++) rs += part[gg * M + tid];
        rowinv[tid] = 1.0f / rs;
    }
    __syncthreads();

    // ---- Phase 5: score accumulation (Am reused) ----
    float accA = 0.0f;
    #pragma unroll
    for (int it = 0; it < 4; it++) {
        const int r = g + NG * it;
        accA += Am[r * M + c] * rowinv[r];
    }
    accA *= rowinv[c];

    float corr = 0.0f;
    if (tid < M) {
        float a = att_s[tid];
        float aa = a * a;
        uint32_t zb = magic_bits(__fmaf_rn(aa, 16.0f, -0.5f));
        float4 v03 = *(const float4*)(smem + (zb * 256u + C403));
        corr = fmaf(aa, v03.y, v03.x) * rowinv[tid];
    }

    float ra  = accA + corr;
    float rbv = dconf * (1.0f / 4096.0f) + attconf * (1.0f / 64.0f);
    #pragma unroll
    for (int off = 16; off > 0; off >>= 1) {
        ra  += __shfl_down_sync(FULL, ra,  off);
        rbv += __shfl_down_sync(FULL, rbv, off);
    }
    if (lane == 0) { wredA[wid] = ra; wredB[wid] = rbv; }
    __syncthreads();

    // ---- Phase 6: score -> one-hot * conf ----
    if (tid == 0) {
        float S = 0.0f, B = 0.0f;
        #pragma unroll
        for (int i = 0; i < NW; i++) { S += wredA[i]; B += wredB[i]; }

        float score = sqrtf(S + 1e-20f);
        uint32_t zb = magic_bits(__fmaf_rn(B, 16.0f, -0.5f));
        int slot = (int)(zb - 0x4B3FFFFFu);
        slot = (slot < 0) ? 0 : ((slot > 18) ? 18 : slot);
        float2 v7 = *(const float2*)(smem + OFF_T7 + (uint32_t)slot * 8u);
        float conf = fmaf(B, v7.y, v7.x);

        float sc = fminf(fmaxf(score, 0.0f), (float)OBJ);
        int   i0 = (int)sc;
        float fr = sc - floorf(sc);
        int   i1 = (i0 + 1 <= OBJ) ? (i0 + 1) : OBJ;

        #pragma unroll
        for (int o = 0; o <= OBJ; o++) {
            float v = 0.0f;
            if (o == i0) v += (1.0f - fr);
            if (o == i1) v += fr;
            out[bi * (OBJ + 1) + o] = conf * v;
        }
    }
}

extern "C" void kernel_launch(void* const* d_in, const int* in_sizes, int n_in,
                              void* d_out, int out_size) {
    const float* boxes = (const float*)d_in[0];   // (n,4,64)
    const float* attn  = (const float*)d_in[1];   // (n,64)
    const float* fwts  = (const float*)d_in[2];   // (16,17)
    float* out = (float*)d_out;                   // (n,11)

    cudaFuncSetAttribute(counter_kernel,
                         cudaFuncAttributeMaxDynamicSharedMemorySize, SMEM_TOTAL);

    const int n = in_sizes[1] / M;                // 128
    counter_kernel<<<n, NT, SMEM_TOTAL>>>(boxes, attn, fwts, out);
}